// round 1
// baseline (speedup 1.0000x reference)
#include <cuda_runtime.h>
#include <cuda_bf16.h>
#include <mma.h>
#include <cstdint>

using namespace nvcuda;

// ---------------- problem constants ----------------
#define N_IMG   32
#define C_IN    256
#define HW      64
#define K_OUT   256
#define X_ELEMS (N_IMG * C_IN * HW * HW)          // 33554432
#define W_ELEMS (K_OUT * C_IN * 3 * 3)            // 589824
#define NXBLK   (X_ELEMS / 16)                    // 2097152
#define NWBLK   (W_ELEMS / 16)                    // 36864

// ---------------- scratch (bf16 quantized tensors) ----------------
__device__ __nv_bfloat16 g_xq[X_ELEMS];   // 64 MiB
__device__ __nv_bfloat16 g_wq[W_ELEMS];   // ~1.1 MiB

// ---------------- NVFP4 fake quant: 16-elem blocks, pow2 scale ----------------
__global__ void quant_nvfp4_kernel(const float* __restrict__ in,
                                   __nv_bfloat16* __restrict__ outq, int nblk) {
    int b = blockIdx.x * blockDim.x + threadIdx.x;
    if (b >= nblk) return;
    const float4* src = reinterpret_cast<const float4*>(in) + (size_t)b * 4;
    float4 t0 = src[0], t1 = src[1], t2 = src[2], t3 = src[3];
    float v[16] = {t0.x, t0.y, t0.z, t0.w, t1.x, t1.y, t1.z, t1.w,
                   t2.x, t2.y, t2.z, t2.w, t3.x, t3.y, t3.z, t3.w};
    float amax = 0.0f;
#pragma unroll
    for (int i = 0; i < 16; ++i) amax = fmaxf(amax, fabsf(v[i]));

    float scale = 1.0f;
    if (amax > 0.0f) {
        float y = fmaxf(amax, 1e-30f) / 6.0f;
        int e;
        float m = frexpf(y, &e);            // y = m * 2^e, m in [0.5, 1)
        scale = ldexpf(1.0f, (m == 0.5f) ? (e - 1) : e);   // exact ceil(log2(y))
    }
    float inv = 1.0f / scale;               // pow2 -> exact

    __align__(16) __nv_bfloat16 q[16];
#pragma unroll
    for (int i = 0; i < 16; ++i) {
        float u = v[i] * inv;
        float a = fabsf(u);
        float g;
        if      (a < 0.25f) g = 0.0f;
        else if (a < 0.75f) g = 0.5f;
        else if (a < 1.25f) g = 1.0f;
        else if (a < 1.75f) g = 1.5f;
        else if (a < 2.5f)  g = 2.0f;
        else if (a < 3.5f)  g = 3.0f;
        else if (a < 5.0f)  g = 4.0f;
        else                g = 6.0f;
        q[i] = __float2bfloat16(copysignf(g, u) * scale);   // exact in bf16
    }
    uint4* dst = reinterpret_cast<uint4*>(outq) + (size_t)b * 2;
    dst[0] = *reinterpret_cast<uint4*>(&q[0]);
    dst[1] = *reinterpret_cast<uint4*>(&q[8]);
}

// ---------------- conv: implicit GEMM, wmma bf16 ----------------
// Block tile: 128 k-out x 128 pixels (2 image rows x 64 cols) for one image.
// Reduction: 16 c-chunks of 16, x 9 (r,s) taps. Warp tile: 32 k x 64 pix.
__global__ void __launch_bounds__(256)
conv3x3_kernel(const __nv_bfloat16* __restrict__ xq,
               const __nv_bfloat16* __restrict__ wq,
               float* __restrict__ out) {
    // xs[input row 0..3][input col -1..64 as 0..65][c 0..15]
    __shared__ __align__(32) __nv_bfloat16 xs[4][66][16];
    // ws[rs 0..8][k 0..127][c 0..15]
    __shared__ __align__(32) __nv_bfloat16 ws[9][128][16];

    const int n  = blockIdx.x;        // image
    const int pt = blockIdx.y;        // pixel tile: rows 2*pt, 2*pt+1
    const int kt = blockIdx.z;        // k tile (0..1)
    const int h0 = pt * 2;
    const int k0 = kt * 128;

    const int tid  = threadIdx.x;
    const int warp = tid >> 5;
    const int wm   = warp & 3;        // k group: 4 groups of 32
    const int wn   = warp >> 2;       // pixel row within tile: 0..1

    // zero the constant left/right padding columns once
    if (tid < 128) {
        int row = tid >> 5;
        int col = ((tid >> 4) & 1) ? 65 : 0;
        int c   = tid & 15;
        xs[row][col][c] = __float2bfloat16(0.0f);
    }

    wmma::fragment<wmma::accumulator, 16, 16, 16, float> acc[2][4];
#pragma unroll
    for (int i = 0; i < 2; ++i)
#pragma unroll
        for (int j = 0; j < 4; ++j) wmma::fill_fragment(acc[i][j], 0.0f);

    const __nv_bfloat16* xbase = xq + (size_t)n * C_IN * HW * HW;

    for (int cc = 0; cc < C_IN; cc += 16) {
        // ---- stage x chunk: 16c x 4 rows x 64 cols (interior) ----
#pragma unroll
        for (int it = 0; it < 2; ++it) {
            int v   = tid + it * 256;          // 0..511
            int c   = v >> 5;                  // 0..15
            int row = (v >> 3) & 3;            // 0..3
            int vc  = v & 7;                   // 8-col vec within the 64
            int gr  = h0 + row - 1;
            uint4 val = make_uint4(0u, 0u, 0u, 0u);
            if ((unsigned)gr < (unsigned)HW)
                val = *reinterpret_cast<const uint4*>(
                    xbase + ((size_t)(cc + c) * HW + gr) * HW + vc * 8);
            const __nv_bfloat16* p = reinterpret_cast<const __nv_bfloat16*>(&val);
#pragma unroll
            for (int t = 0; t < 8; ++t) xs[row][1 + vc * 8 + t][c] = p[t];
        }
        // ---- stage w chunk: 128k x 16c x 9rs (contiguous 144 elems per k) ----
        {
            int k    = tid >> 1;
            int half = tid & 1;
            const uint4* src = reinterpret_cast<const uint4*>(
                wq + ((size_t)(k0 + k) * C_IN + cc) * 9) + half * 9;
#pragma unroll
            for (int q8 = 0; q8 < 9; ++q8) {
                uint4 val = src[q8];
                const __nv_bfloat16* p = reinterpret_cast<const __nv_bfloat16*>(&val);
#pragma unroll
                for (int t = 0; t < 8; ++t) {
                    int j  = half * 72 + q8 * 8 + t;
                    int c  = j / 9;
                    int rs = j % 9;
                    ws[rs][k][c] = p[t];
                }
            }
        }
        __syncthreads();

        // ---- compute: 9 taps x 1 c16 step each ----
#pragma unroll
        for (int r = 0; r < 3; ++r) {
#pragma unroll
            for (int s = 0; s < 3; ++s) {
                const int rs = r * 3 + s;
                wmma::fragment<wmma::matrix_a, 16, 16, 16, __nv_bfloat16, wmma::row_major> a0, a1;
                wmma::load_matrix_sync(a0, &ws[rs][wm * 32 + 0][0], 16);
                wmma::load_matrix_sync(a1, &ws[rs][wm * 32 + 16][0], 16);
#pragma unroll
                for (int j = 0; j < 4; ++j) {
                    wmma::fragment<wmma::matrix_b, 16, 16, 16, __nv_bfloat16, wmma::col_major> b;
                    wmma::load_matrix_sync(b, &xs[wn + r][j * 16 + s][0], 16);
                    wmma::mma_sync(acc[0][j], a0, b, acc[0][j]);
                    wmma::mma_sync(acc[1][j], a1, b, acc[1][j]);
                }
            }
        }
        __syncthreads();
    }

    // ---- epilogue: out[n][k][h][w], fp32 ----
    float* obase = out + (((size_t)n * K_OUT + k0 + wm * 32) * HW + (h0 + wn)) * HW;
#pragma unroll
    for (int i = 0; i < 2; ++i)
#pragma unroll
        for (int j = 0; j < 4; ++j)
            wmma::store_matrix_sync(obase + (size_t)i * 16 * HW * HW + j * 16,
                                    acc[i][j], HW * HW, wmma::mem_row_major);
}

// ---------------- launch ----------------
extern "C" void kernel_launch(void* const* d_in, const int* in_sizes, int n_in,
                              void* d_out, int out_size) {
    const float* x = (const float*)d_in[0];
    const float* w = (const float*)d_in[1];
    if (in_sizes[0] != X_ELEMS) {   // defensive: pick by size
        x = (const float*)d_in[1];
        w = (const float*)d_in[0];
    }

    void* xq_ptr = nullptr;
    void* wq_ptr = nullptr;
    cudaGetSymbolAddress(&xq_ptr, g_xq);
    cudaGetSymbolAddress(&wq_ptr, g_wq);
    __nv_bfloat16* xq = (__nv_bfloat16*)xq_ptr;
    __nv_bfloat16* wq = (__nv_bfloat16*)wq_ptr;

    quant_nvfp4_kernel<<<NXBLK / 256, 256>>>(x, xq, NXBLK);
    quant_nvfp4_kernel<<<(NWBLK + 255) / 256, 256>>>(w, wq, NWBLK);

    dim3 grid(N_IMG, HW / 2, K_OUT / 128);   // (32, 32, 2)
    conv3x3_kernel<<<grid, 256>>>(xq, wq, (float*)d_out);
}

// round 2
// speedup vs baseline: 3.1979x; 3.1979x over previous
#include <cuda_runtime.h>
#include <cuda_bf16.h>
#include <mma.h>
#include <cstdint>

using namespace nvcuda;

// ---------------- problem constants ----------------
#define N_IMG   32
#define C_IN    256
#define HW      64
#define K_OUT   256
#define X_ELEMS (N_IMG * C_IN * HW * HW)          // 33554432
#define W_ELEMS (K_OUT * C_IN * 9)                // 589824
#define NWBLK   (W_ELEMS / 16)                    // 36864

// ---------------- scratch ----------------
__device__ __nv_bfloat16 g_xq[X_ELEMS];           // NHWC: ((n*64+h)*64+w)*256 + c
__device__ __nv_bfloat16 g_wq2[9 * K_OUT * C_IN]; // [rs][k][c]

// ---------------- fake-quant core (exact pow2 scale + RTN E2M1) ----------------
__device__ __forceinline__ void quant16(const float* __restrict__ v,
                                        __nv_bfloat16* __restrict__ q) {
    float amax = 0.0f;
#pragma unroll
    for (int i = 0; i < 16; ++i) amax = fmaxf(amax, fabsf(v[i]));
    float scale = 1.0f;
    if (amax > 0.0f) {
        float y = fmaxf(amax, 1e-30f) / 6.0f;
        int e;
        float m = frexpf(y, &e);                               // y = m*2^e, m in [0.5,1)
        scale = ldexpf(1.0f, (m == 0.5f) ? (e - 1) : e);       // exact ceil(log2 y)
    }
    float inv = 1.0f / scale;
#pragma unroll
    for (int i = 0; i < 16; ++i) {
        float u = v[i] * inv;
        float a = fabsf(u);
        float g;
        if      (a < 0.25f) g = 0.0f;
        else if (a < 0.75f) g = 0.5f;
        else if (a < 1.25f) g = 1.0f;
        else if (a < 1.75f) g = 1.5f;
        else if (a < 2.5f)  g = 2.0f;
        else if (a < 3.5f)  g = 3.0f;
        else if (a < 5.0f)  g = 4.0f;
        else                g = 6.0f;
        q[i] = __float2bfloat16(copysignf(g, u) * scale);      // exact in bf16
    }
}

// ---------------- x quant -> NHWC ----------------
// grid (32, 16, 4): (n, c-group of 16, h-group of 16). 256 threads.
__global__ void __launch_bounds__(256)
quant_x_nhwc(const float* __restrict__ x, __nv_bfloat16* __restrict__ xq) {
    __shared__ __nv_bfloat16 st[16][64][16];   // [h'][w][c'] 32KB
    const int n  = blockIdx.x;
    const int cg = blockIdx.y;
    const int hg = blockIdx.z;
    const int t  = threadIdx.x;

#pragma unroll
    for (int i = 0; i < 4; ++i) {
        int qb = t + 256 * i;               // 0..1023 -> (c', h', wb)
        int c1 = qb >> 6;
        int h1 = (qb >> 2) & 15;
        int wb = qb & 3;
        const float4* src = reinterpret_cast<const float4*>(
            x + ((((size_t)n * C_IN + cg * 16 + c1) * HW + hg * 16 + h1) * HW + wb * 16));
        float4 t0 = src[0], t1 = src[1], t2 = src[2], t3 = src[3];
        float v[16] = {t0.x, t0.y, t0.z, t0.w, t1.x, t1.y, t1.z, t1.w,
                       t2.x, t2.y, t2.z, t2.w, t3.x, t3.y, t3.z, t3.w};
        __nv_bfloat16 q[16];
        quant16(v, q);
#pragma unroll
        for (int j = 0; j < 16; ++j) st[h1][wb * 16 + j][c1] = q[j];
    }
    __syncthreads();
#pragma unroll
    for (int i = 0; i < 4; ++i) {
        int p  = t + 256 * i;               // (h', w)
        int h1 = p >> 6;
        int w  = p & 63;
        const uint4* s = reinterpret_cast<const uint4*>(&st[h1][w][0]);
        uint4* d = reinterpret_cast<uint4*>(
            xq + (((size_t)n * HW + hg * 16 + h1) * HW + w) * C_IN + cg * 16);
        d[0] = s[0];
        d[1] = s[1];
    }
}

// ---------------- w quant + repack -> [rs][k][c] ----------------
__global__ void quant_w_repack(const float* __restrict__ w,
                               __nv_bfloat16* __restrict__ wq2) {
    int b = blockIdx.x * blockDim.x + threadIdx.x;
    if (b >= NWBLK) return;
    const float4* src = reinterpret_cast<const float4*>(w) + (size_t)b * 4;
    float4 t0 = src[0], t1 = src[1], t2 = src[2], t3 = src[3];
    float v[16] = {t0.x, t0.y, t0.z, t0.w, t1.x, t1.y, t1.z, t1.w,
                   t2.x, t2.y, t2.z, t2.w, t3.x, t3.y, t3.z, t3.w};
    __nv_bfloat16 q[16];
    quant16(v, q);
#pragma unroll
    for (int i = 0; i < 16; ++i) {
        int f  = b * 16 + i;                // OIHW flat: ((k*256 + c)*9 + rs)
        int k  = f / 2304;
        int r2 = f - k * 2304;
        int c  = r2 / 9;
        int rs = r2 - c * 9;
        wq2[((size_t)rs * K_OUT + k) * C_IN + c] = q[i];
    }
}

// ---------------- cp.async helpers ----------------
__device__ __forceinline__ void cp_async16(void* dst, const void* src, bool pred) {
    uint32_t d = (uint32_t)__cvta_generic_to_shared(dst);
    int sz = pred ? 16 : 0;
    asm volatile("cp.async.cg.shared.global [%0], [%1], 16, %2;\n"
                 :: "r"(d), "l"(src), "r"(sz));
}
__device__ __forceinline__ void cp_commit() {
    asm volatile("cp.async.commit_group;\n");
}
template <int N>
__device__ __forceinline__ void cp_wait() {
    asm volatile("cp.async.wait_group %0;\n" :: "n"(N));
}

// ---------------- conv: implicit GEMM, wmma bf16, double-buffered ----------------
// CTA tile: 128 kout x (4 rows x 64 cols). 8 warps: wm(2) x wn(4), warp = 64k x 64pix.
// smem per buffer: xs[6][66][16] + ws[9][128][16]
#define XS_ELEMS (6 * 66 * 16)      // 6336
#define WS_ELEMS (9 * 128 * 16)     // 18432
#define SBUF     (XS_ELEMS + WS_ELEMS)
#define SMEM_BYTES (2 * SBUF * 2)   // 99072

__device__ __forceinline__ void stage_chunk(__nv_bfloat16* xsb, __nv_bfloat16* wsb,
                                            const __nv_bfloat16* __restrict__ xq,
                                            const __nv_bfloat16* __restrict__ wq2,
                                            int n, int h0, int k0, int cc, int t) {
    // x: 6 rows x 64 cols x 16c = 768 x 16B
#pragma unroll
    for (int i = 0; i < 3; ++i) {
        int idx  = t + 256 * i;
        int pair = idx >> 1;
        int half = idx & 1;
        int row  = pair >> 6;
        int col  = pair & 63;
        int gr   = h0 - 1 + row;
        bool ok  = (unsigned)gr < (unsigned)HW;
        int grc  = ok ? gr : 0;
        cp_async16(&xsb[(row * 66 + 1 + col) * 16 + half * 8],
                   xq + (((size_t)n * HW + grc) * HW + col) * C_IN + cc + half * 8, ok);
    }
    // w: 9 rs x 128 k x 16c = 2304 x 16B
#pragma unroll
    for (int i = 0; i < 9; ++i) {
        int idx  = t + 256 * i;
        int pair = idx >> 1;
        int half = idx & 1;
        int rs   = pair >> 7;
        int k    = pair & 127;
        cp_async16(&wsb[(rs * 128 + k) * 16 + half * 8],
                   wq2 + ((size_t)rs * K_OUT + k0 + k) * C_IN + cc + half * 8, true);
    }
}

__global__ void __launch_bounds__(256, 1)
conv3x3_kernel(const __nv_bfloat16* __restrict__ xq,
               const __nv_bfloat16* __restrict__ wq2,
               float* __restrict__ out) {
    extern __shared__ __nv_bfloat16 smem[];

    const int n  = blockIdx.x;
    const int ht = blockIdx.y;     // 0..15, 4 output rows each
    const int kt = blockIdx.z;     // 0..1
    const int h0 = ht * 4;
    const int k0 = kt * 128;

    const int t    = threadIdx.x;
    const int warp = t >> 5;
    const int wm   = warp & 1;     // k half: 64 k's
    const int wn   = warp >> 1;    // output row 0..3

    // zero left/right halo columns (both buffers), never touched by staging
    if (t < 24) {
        int buf = t / 12;
        int rr  = (t % 12) >> 1;
        int col = (t & 1) ? 65 : 0;
        uint4* p = reinterpret_cast<uint4*>(&smem[buf * SBUF + (rr * 66 + col) * 16]);
        p[0] = make_uint4(0, 0, 0, 0);
        p[1] = make_uint4(0, 0, 0, 0);
    }

    wmma::fragment<wmma::accumulator, 16, 16, 16, float> acc[4][4];
#pragma unroll
    for (int i = 0; i < 4; ++i)
#pragma unroll
        for (int j = 0; j < 4; ++j) wmma::fill_fragment(acc[i][j], 0.0f);

    stage_chunk(smem, smem + XS_ELEMS, xq, wq2, n, h0, k0, 0, t);
    cp_commit();

#pragma unroll 1
    for (int it = 0; it < 16; ++it) {
        int cur = it & 1;
        if (it + 1 < 16) {
            int nxt = (it + 1) & 1;
            stage_chunk(smem + nxt * SBUF, smem + nxt * SBUF + XS_ELEMS,
                        xq, wq2, n, h0, k0, (it + 1) * 16, t);
            cp_commit();
            cp_wait<1>();
        } else {
            cp_wait<0>();
        }
        __syncthreads();

        const __nv_bfloat16* xsb = smem + cur * SBUF;
        const __nv_bfloat16* wsb = xsb + XS_ELEMS;

#pragma unroll
        for (int r = 0; r < 3; ++r) {
#pragma unroll
            for (int s = 0; s < 3; ++s) {
                const int rs = r * 3 + s;
                wmma::fragment<wmma::matrix_a, 16, 16, 16, __nv_bfloat16, wmma::row_major> a[4];
#pragma unroll
                for (int i = 0; i < 4; ++i)
                    wmma::load_matrix_sync(a[i], &wsb[(rs * 128 + wm * 64 + i * 16) * 16], 16);
#pragma unroll
                for (int j = 0; j < 4; ++j) {
                    wmma::fragment<wmma::matrix_b, 16, 16, 16, __nv_bfloat16, wmma::col_major> b;
                    wmma::load_matrix_sync(b, &xsb[((wn + r) * 66 + j * 16 + s) * 16], 16);
#pragma unroll
                    for (int i = 0; i < 4; ++i)
                        wmma::mma_sync(acc[i][j], a[i], b, acc[i][j]);
                }
            }
        }
        __syncthreads();
    }

    // epilogue: out[n][k][h][w]
    float* obase = out + (((size_t)n * K_OUT + k0 + wm * 64) * HW + h0 + wn) * HW;
#pragma unroll
    for (int i = 0; i < 4; ++i)
#pragma unroll
        for (int j = 0; j < 4; ++j)
            wmma::store_matrix_sync(obase + (size_t)i * 16 * HW * HW + j * 16,
                                    acc[i][j], HW * HW, wmma::mem_row_major);
}

// ---------------- launch ----------------
extern "C" void kernel_launch(void* const* d_in, const int* in_sizes, int n_in,
                              void* d_out, int out_size) {
    const float* x = (const float*)d_in[0];
    const float* w = (const float*)d_in[1];
    if (in_sizes[0] != X_ELEMS) {
        x = (const float*)d_in[1];
        w = (const float*)d_in[0];
    }

    void* xq_ptr = nullptr;
    void* wq_ptr = nullptr;
    cudaGetSymbolAddress(&xq_ptr, g_xq);
    cudaGetSymbolAddress(&wq_ptr, g_wq2);
    __nv_bfloat16* xq = (__nv_bfloat16*)xq_ptr;
    __nv_bfloat16* wq2 = (__nv_bfloat16*)wq_ptr;

    cudaFuncSetAttribute(conv3x3_kernel,
                         cudaFuncAttributeMaxDynamicSharedMemorySize, SMEM_BYTES);

    quant_x_nhwc<<<dim3(N_IMG, 16, 4), 256>>>(x, xq);
    quant_w_repack<<<(NWBLK + 255) / 256, 256>>>(w, wq2);

    dim3 grid(N_IMG, 16, 2);
    conv3x3_kernel<<<grid, 256, SMEM_BYTES>>>(xq, wq2, (float*)d_out);
}

// round 3
// speedup vs baseline: 4.1205x; 1.2885x over previous
#include <cuda_runtime.h>
#include <cuda_bf16.h>
#include <cstdint>

// ---------------- problem constants ----------------
#define N_IMG   32
#define C_IN    256
#define HW      64
#define K_OUT   256
#define X_ELEMS (N_IMG * C_IN * HW * HW)          // 33554432
#define W_ELEMS (K_OUT * C_IN * 9)                // 589824
#define NWBLK   (W_ELEMS / 16)                    // 36864

// ---------------- scratch ----------------
__device__ __nv_bfloat16 g_xq[X_ELEMS];           // NHWC: ((n*64+h)*64+w)*256 + c
__device__ __nv_bfloat16 g_wq2[9 * K_OUT * C_IN]; // [rs][k][c]

// ---------------- fake-quant core (exact pow2 scale + RTN E2M1) ----------------
__device__ __forceinline__ void quant16(const float* __restrict__ v,
                                        __nv_bfloat16* __restrict__ q) {
    float amax = 0.0f;
#pragma unroll
    for (int i = 0; i < 16; ++i) amax = fmaxf(amax, fabsf(v[i]));
    float scale = 1.0f;
    if (amax > 0.0f) {
        float y = fmaxf(amax, 1e-30f) / 6.0f;
        int e;
        float m = frexpf(y, &e);                               // y = m*2^e, m in [0.5,1)
        scale = ldexpf(1.0f, (m == 0.5f) ? (e - 1) : e);       // exact ceil(log2 y)
    }
    float inv = 1.0f / scale;
#pragma unroll
    for (int i = 0; i < 16; ++i) {
        float u = v[i] * inv;
        float a = fabsf(u);
        float g;
        if      (a < 0.25f) g = 0.0f;
        else if (a < 0.75f) g = 0.5f;
        else if (a < 1.25f) g = 1.0f;
        else if (a < 1.75f) g = 1.5f;
        else if (a < 2.5f)  g = 2.0f;
        else if (a < 3.5f)  g = 3.0f;
        else if (a < 5.0f)  g = 4.0f;
        else                g = 6.0f;
        q[i] = __float2bfloat16(copysignf(g, u) * scale);      // exact in bf16
    }
}

// ---------------- x quant -> NHWC, conflict-free smem transpose ----------------
// grid (32, 64) = (n, h). 256 threads. Each thread quantizes a channel PAIR
// over two 16-w blocks, writing packed u32 (c even|odd) into buf[pixel][cpair].
__global__ void __launch_bounds__(256)
quant_x_nhwc(const float* __restrict__ x, __nv_bfloat16* __restrict__ xq) {
    __shared__ uint32_t buf[64][132];    // pitch 132: write bank=(4p+cp)%32, read uint4 ok
    const int n = blockIdx.x;
    const int h = blockIdx.y;
    const int t = threadIdx.x;
    const int cp  = t & 127;             // channel pair: c = 2*cp, 2*cp+1
    const int wb0 = t >> 7;              // 0..1

#pragma unroll
    for (int wbi = 0; wbi < 2; ++wbi) {
        int wb = wb0 + wbi * 2;          // 0..3
        const float* base = x + (((size_t)n * C_IN + 2 * cp) * HW + h) * HW + wb * 16;
        const float4* p0 = reinterpret_cast<const float4*>(base);
        const float4* p1 = reinterpret_cast<const float4*>(base + (size_t)HW * HW);
        float v0[16], v1[16];
#pragma unroll
        for (int i = 0; i < 4; ++i) {
            float4 a = p0[i];
            v0[i * 4 + 0] = a.x; v0[i * 4 + 1] = a.y; v0[i * 4 + 2] = a.z; v0[i * 4 + 3] = a.w;
            float4 b = p1[i];
            v1[i * 4 + 0] = b.x; v1[i * 4 + 1] = b.y; v1[i * 4 + 2] = b.z; v1[i * 4 + 3] = b.w;
        }
        __nv_bfloat16 q0[16], q1[16];
        quant16(v0, q0);
        quant16(v1, q1);
#pragma unroll
        for (int j = 0; j < 16; ++j) {
            __nv_bfloat162 pk;
            pk.x = q0[j];                // channel 2cp  -> low 2 bytes
            pk.y = q1[j];                // channel 2cp+1-> high 2 bytes
            buf[wb * 16 + j][cp] = *reinterpret_cast<uint32_t*>(&pk);
        }
    }
    __syncthreads();

#pragma unroll
    for (int i = 0; i < 8; ++i) {
        int idx = t + 256 * i;           // 0..2047
        int p   = idx >> 5;              // pixel 0..63
        int q   = idx & 31;              // 16B quad within pixel
        uint4 val = *reinterpret_cast<const uint4*>(&buf[p][q * 4]);
        uint4* dst = reinterpret_cast<uint4*>(
            xq + (((size_t)n * HW + h) * HW + p) * C_IN);
        dst[q] = val;
    }
}

// ---------------- w quant + repack -> [rs][k][c] ----------------
__global__ void quant_w_repack(const float* __restrict__ w,
                               __nv_bfloat16* __restrict__ wq2) {
    int b = blockIdx.x * blockDim.x + threadIdx.x;
    if (b >= NWBLK) return;
    const float4* src = reinterpret_cast<const float4*>(w) + (size_t)b * 4;
    float4 t0 = src[0], t1 = src[1], t2 = src[2], t3 = src[3];
    float v[16] = {t0.x, t0.y, t0.z, t0.w, t1.x, t1.y, t1.z, t1.w,
                   t2.x, t2.y, t2.z, t2.w, t3.x, t3.y, t3.z, t3.w};
    __nv_bfloat16 q[16];
    quant16(v, q);
#pragma unroll
    for (int i = 0; i < 16; ++i) {
        int f  = b * 16 + i;                // OIHW flat: ((k*256 + c)*9 + rs)
        int k  = f / 2304;
        int r2 = f - k * 2304;
        int c  = r2 / 9;
        int rs = r2 - c * 9;
        wq2[((size_t)rs * K_OUT + k) * C_IN + c] = q[i];
    }
}

// ---------------- PTX helpers ----------------
__device__ __forceinline__ void cp_async16(void* dst, const void* src, bool pred) {
    uint32_t d = (uint32_t)__cvta_generic_to_shared(dst);
    int sz = pred ? 16 : 0;
    asm volatile("cp.async.cg.shared.global [%0], [%1], 16, %2;\n"
                 :: "r"(d), "l"(src), "r"(sz));
}
__device__ __forceinline__ void cp_commit() {
    asm volatile("cp.async.commit_group;\n");
}
template <int N>
__device__ __forceinline__ void cp_wait() {
    asm volatile("cp.async.wait_group %0;\n" :: "n"(N));
}
__device__ __forceinline__ void ldsm_x4(uint32_t addr, uint32_t& r0, uint32_t& r1,
                                        uint32_t& r2, uint32_t& r3) {
    asm volatile("ldmatrix.sync.aligned.m8n8.x4.shared.b16 {%0,%1,%2,%3}, [%4];"
                 : "=r"(r0), "=r"(r1), "=r"(r2), "=r"(r3) : "r"(addr));
}
__device__ __forceinline__ void ldsm_x2(uint32_t addr, uint32_t& r0, uint32_t& r1) {
    asm volatile("ldmatrix.sync.aligned.m8n8.x2.shared.b16 {%0,%1}, [%2];"
                 : "=r"(r0), "=r"(r1) : "r"(addr));
}
__device__ __forceinline__ void mma16816(float* d, const uint32_t* a,
                                         uint32_t b0, uint32_t b1) {
    asm volatile("mma.sync.aligned.m16n8k16.row.col.f32.bf16.bf16.f32 "
                 "{%0,%1,%2,%3}, {%4,%5,%6,%7}, {%8,%9}, {%0,%1,%2,%3};"
                 : "+f"(d[0]), "+f"(d[1]), "+f"(d[2]), "+f"(d[3])
                 : "r"(a[0]), "r"(a[1]), "r"(a[2]), "r"(a[3]), "r"(b0), "r"(b1));
}

// ---------------- conv: implicit GEMM, raw mma, padded smem ----------------
// CTA: 128 kout x (4 rows x 64 cols). 8 warps: wm(2 k-halves of 64) x wn(4 rows).
// smem rows padded to 24 bf16 (48B) -> conflict-free ldmatrix.
#define CPAD 24
#define XS_ELEMS (6 * 66 * CPAD)        // 9504
#define WS_ELEMS (9 * 128 * CPAD)       // 27648
#define SBUF     (XS_ELEMS + WS_ELEMS)  // 37152
#define SMEM_BYTES (2 * SBUF * 2)       // 148608

__device__ __forceinline__ void stage_chunk(__nv_bfloat16* xsb, __nv_bfloat16* wsb,
                                            const __nv_bfloat16* __restrict__ xq,
                                            const __nv_bfloat16* __restrict__ wq2,
                                            int n, int h0, int k0, int cc, int t) {
    // x: 6 rows x 64 cols x 16c, 16B per copy
#pragma unroll
    for (int i = 0; i < 3; ++i) {
        int idx  = t + 256 * i;
        int pair = idx >> 1;
        int half = idx & 1;
        int row  = pair >> 6;
        int col  = pair & 63;
        int gr   = h0 - 1 + row;
        bool ok  = (unsigned)gr < (unsigned)HW;
        int grc  = ok ? gr : 0;
        cp_async16(&xsb[(row * 66 + 1 + col) * CPAD + half * 8],
                   xq + (((size_t)n * HW + grc) * HW + col) * C_IN + cc + half * 8, ok);
    }
    // w: 9 rs x 128 k x 16c
#pragma unroll
    for (int i = 0; i < 9; ++i) {
        int idx  = t + 256 * i;
        int pair = idx >> 1;
        int half = idx & 1;
        int rs   = pair >> 7;
        int k    = pair & 127;
        cp_async16(&wsb[(rs * 128 + k) * CPAD + half * 8],
                   wq2 + ((size_t)rs * K_OUT + k0 + k) * C_IN + cc + half * 8, true);
    }
}

__global__ void __launch_bounds__(256, 1)
conv3x3_kernel(const __nv_bfloat16* __restrict__ xq,
               const __nv_bfloat16* __restrict__ wq2,
               float* __restrict__ out) {
    extern __shared__ __nv_bfloat16 smem[];

    const int n  = blockIdx.x;
    const int ht = blockIdx.y;     // 0..15
    const int kt = blockIdx.z;     // 0..1
    const int h0 = ht * 4;
    const int k0 = kt * 128;

    const int t    = threadIdx.x;
    const int lane = t & 31;
    const int warp = t >> 5;
    const int wm   = warp & 1;     // k half (64 k)
    const int wn   = warp >> 1;    // output row 0..3

    // zero left/right halo columns in both buffers
    if (t < 24) {
        int buf = t / 12;
        int rr  = (t % 12) >> 1;
        int col = (t & 1) ? 65 : 0;
        uint4* p = reinterpret_cast<uint4*>(&smem[buf * SBUF + (rr * 66 + col) * CPAD]);
        p[0] = make_uint4(0, 0, 0, 0);
        p[1] = make_uint4(0, 0, 0, 0);
    }

    // ldmatrix per-lane offsets (in bf16 elements)
    const int a_off = (lane & 15) * CPAD + (lane >> 4) * 8;          // A x4
    const int b_off = (lane & 7) * CPAD + ((lane >> 3) & 1) * 8;     // B x2 (lanes 0..15)

    float acc[4][8][4];
#pragma unroll
    for (int i = 0; i < 4; ++i)
#pragma unroll
        for (int j = 0; j < 8; ++j)
#pragma unroll
            for (int v = 0; v < 4; ++v) acc[i][j][v] = 0.0f;

    stage_chunk(smem, smem + XS_ELEMS, xq, wq2, n, h0, k0, 0, t);
    cp_commit();

    const uint32_t smem_u32 = (uint32_t)__cvta_generic_to_shared(smem);

#pragma unroll 1
    for (int it = 0; it < 16; ++it) {
        int cur = it & 1;
        if (it + 1 < 16) {
            int nxt = (it + 1) & 1;
            stage_chunk(smem + nxt * SBUF, smem + nxt * SBUF + XS_ELEMS,
                        xq, wq2, n, h0, k0, (it + 1) * 16, t);
            cp_commit();
            cp_wait<1>();
        } else {
            cp_wait<0>();
        }
        __syncthreads();

        const uint32_t xs_b = smem_u32 + (cur * SBUF) * 2;
        const uint32_t ws_b = xs_b + XS_ELEMS * 2;

#pragma unroll
        for (int r = 0; r < 3; ++r) {
#pragma unroll
            for (int s = 0; s < 3; ++s) {
                const int rs = r * 3 + s;
                uint32_t a[4][4];
#pragma unroll
                for (int i = 0; i < 4; ++i) {
                    uint32_t addr = ws_b +
                        ((rs * 128 + wm * 64 + i * 16) * CPAD + a_off) * 2;
                    ldsm_x4(addr, a[i][0], a[i][1], a[i][2], a[i][3]);
                }
#pragma unroll
                for (int jn = 0; jn < 8; ++jn) {
                    uint32_t baddr = xs_b +
                        (((wn + r) * 66 + jn * 8 + s) * CPAD + b_off) * 2;
                    uint32_t b0, b1;
                    ldsm_x2(baddr, b0, b1);
#pragma unroll
                    for (int i = 0; i < 4; ++i)
                        mma16816(acc[i][jn], a[i], b0, b1);
                }
            }
        }
        __syncthreads();
    }

    // epilogue: C frag (m16n8): lane g=lane/4 holds cols 2t,2t+1 at rows g, g+8
    const int g  = lane >> 2;
    const int tc = lane & 3;
    const size_t kbase = (size_t)n * K_OUT + k0 + wm * 64;
#pragma unroll
    for (int i = 0; i < 4; ++i) {
#pragma unroll
        for (int jn = 0; jn < 8; ++jn) {
            size_t o0 = ((kbase + i * 16 + g) * HW + h0 + wn) * HW + jn * 8 + 2 * tc;
            size_t o1 = o0 + (size_t)8 * HW * HW;
            *reinterpret_cast<float2*>(out + o0) = make_float2(acc[i][jn][0], acc[i][jn][1]);
            *reinterpret_cast<float2*>(out + o1) = make_float2(acc[i][jn][2], acc[i][jn][3]);
        }
    }
}

// ---------------- launch ----------------
extern "C" void kernel_launch(void* const* d_in, const int* in_sizes, int n_in,
                              void* d_out, int out_size) {
    const float* x = (const float*)d_in[0];
    const float* w = (const float*)d_in[1];
    if (in_sizes[0] != X_ELEMS) {
        x = (const float*)d_in[1];
        w = (const float*)d_in[0];
    }

    void* xq_ptr = nullptr;
    void* wq_ptr = nullptr;
    cudaGetSymbolAddress(&xq_ptr, g_xq);
    cudaGetSymbolAddress(&wq_ptr, g_wq2);
    __nv_bfloat16* xq = (__nv_bfloat16*)xq_ptr;
    __nv_bfloat16* wq2 = (__nv_bfloat16*)wq_ptr;

    cudaFuncSetAttribute(conv3x3_kernel,
                         cudaFuncAttributeMaxDynamicSharedMemorySize, SMEM_BYTES);

    quant_x_nhwc<<<dim3(N_IMG, HW), 256>>>(x, xq);
    quant_w_repack<<<(NWBLK + 255) / 256, 256>>>(w, wq2);

    dim3 grid(N_IMG, 16, 2);
    conv3x3_kernel<<<grid, 256, SMEM_BYTES>>>(xq, wq2, (float*)d_out);
}